// round 4
// baseline (speedup 1.0000x reference)
#include <cuda_runtime.h>
#include <cuda_bf16.h>
#include <math.h>

// Problem constants
#define Bn 32
#define Tn 1024
#define INn 256
#define Hn 128
#define F2n 256
#define NG 512           // 4*H gates per direction
#define NGATES 1024      // both directions
#define Mrows (Tn*Bn)    // 32768
#define PF 4             // gin prefetch depth

typedef unsigned long long u64;

// ---------------- device scratch (no allocs allowed) ----------------
__device__ float g_gates[(size_t)Mrows * NGATES];   // [m][dir*512+g], m = t*32+b
__device__ float g_out1[(size_t)Mrows * F2n];       // [t*32+b][256]
__device__ float g_out2[(size_t)Mrows * F2n];
__device__ float g_kq[Bn * F2n];
__device__ float g_qbk[Bn];
__device__ float g_vw[4 * F2n];
__device__ float g_vb[4];

// ---------------- helpers ----------------
__device__ __forceinline__ float tanh_fast(float x) {
    float r;
    asm("tanh.approx.f32 %0, %1;" : "=f"(r) : "f"(x));
    return r;
}
__device__ __forceinline__ unsigned f2tf32(float f) {
    unsigned u;
    asm("cvt.rna.tf32.f32 %0, %1;" : "=r"(u) : "f"(f));
    return u;
}
__device__ __forceinline__ void ffma2(u64& acc, u64 a, u64 b) {
    asm("fma.rn.f32x2 %0, %1, %2, %0;" : "+l"(acc) : "l"(a), "l"(b));
}
__device__ __forceinline__ u64 packf2(float lo, float hi) {
    u64 r;
    asm("mov.b64 %0, {%1, %2};" : "=l"(r) : "f"(lo), "f"(hi));
    return r;
}
__device__ __forceinline__ void unpackf2(u64 v, float& lo, float& hi) {
    asm("mov.b64 {%0, %1}, %2;" : "=f"(lo), "=f"(hi) : "l"(v));
}

// ---------------- tf32 tensor-core GEMM: gates = A @ W^T + (bi+bh) ----------------
__device__ __forceinline__ int sidx(int r, int k) {
    return r * 32 + ((((k >> 2) ^ (r & 7)) & 7) << 2) + (k & 3);
}

__global__ __launch_bounds__(256) void gemm_tf32(
    const float* __restrict__ A, size_t sB, size_t sT,
    const float* __restrict__ W,
    const float* __restrict__ bi, const float* __restrict__ bh,
    float* __restrict__ C)
{
    __shared__ unsigned sA[128 * 32];
    __shared__ unsigned sW[128 * 32];

    int tid = threadIdx.x;
    int wid = tid >> 5, lane = tid & 31;
    int g = lane >> 2, q = lane & 3;
    int warpM = wid & 1, warpN = wid >> 1;
    int mBase = blockIdx.y * 128;
    int nBase = blockIdx.x * 128;

    float acc[4][4][4];
#pragma unroll
    for (int mb = 0; mb < 4; mb++)
#pragma unroll
        for (int nb = 0; nb < 4; nb++)
#pragma unroll
            for (int i = 0; i < 4; i++) acc[mb][nb][i] = 0.f;

    int lrow = tid >> 3;
    int lseg = tid & 7;

    const float* Arows[4];
    const float* Wrows[4];
#pragma unroll
    for (int i = 0; i < 4; i++) {
        int r = lrow + 32 * i;
        int m = mBase + r;
        int bb = m & 31, tt = m >> 5;
        Arows[i] = A + (size_t)bb * sB + (size_t)tt * sT + lseg * 4;
        Wrows[i] = W + (size_t)(nBase + r) * 256 + lseg * 4;
    }
    int soff[4];
#pragma unroll
    for (int i = 0; i < 4; i++) {
        int r = lrow + 32 * i;
        soff[i] = r * 32 + (((lseg ^ (r & 7)) & 7) << 2);
    }

    float4 av[4], wv[4];
#pragma unroll
    for (int i = 0; i < 4; i++) {
        av[i] = *(const float4*)(Arows[i]);
        wv[i] = *(const float4*)(Wrows[i]);
    }

    for (int kb = 0; kb < 256; kb += 32) {
#pragma unroll
        for (int i = 0; i < 4; i++) {
            *(uint4*)&sA[soff[i]] = make_uint4(f2tf32(av[i].x), f2tf32(av[i].y), f2tf32(av[i].z), f2tf32(av[i].w));
            *(uint4*)&sW[soff[i]] = make_uint4(f2tf32(wv[i].x), f2tf32(wv[i].y), f2tf32(wv[i].z), f2tf32(wv[i].w));
        }
        __syncthreads();

        if (kb + 32 < 256) {
#pragma unroll
            for (int i = 0; i < 4; i++) {
                av[i] = *(const float4*)(Arows[i] + kb + 32);
                wv[i] = *(const float4*)(Wrows[i] + kb + 32);
            }
        }

#pragma unroll
        for (int kk = 0; kk < 4; kk++) {
            unsigned af[4][4], bf[4][2];
#pragma unroll
            for (int mb = 0; mb < 4; mb++) {
                int r = warpM * 64 + mb * 16 + g;
                af[mb][0] = sA[sidx(r,     kk * 8 + q)];
                af[mb][1] = sA[sidx(r + 8, kk * 8 + q)];
                af[mb][2] = sA[sidx(r,     kk * 8 + q + 4)];
                af[mb][3] = sA[sidx(r + 8, kk * 8 + q + 4)];
            }
#pragma unroll
            for (int nb = 0; nb < 4; nb++) {
                int n = warpN * 32 + nb * 8 + g;
                bf[nb][0] = sW[sidx(n, kk * 8 + q)];
                bf[nb][1] = sW[sidx(n, kk * 8 + q + 4)];
            }
#pragma unroll
            for (int mb = 0; mb < 4; mb++)
#pragma unroll
                for (int nb = 0; nb < 4; nb++) {
                    asm volatile(
                        "mma.sync.aligned.m16n8k8.row.col.f32.tf32.tf32.f32 "
                        "{%0,%1,%2,%3}, {%4,%5,%6,%7}, {%8,%9}, {%0,%1,%2,%3};"
                        : "+f"(acc[mb][nb][0]), "+f"(acc[mb][nb][1]),
                          "+f"(acc[mb][nb][2]), "+f"(acc[mb][nb][3])
                        : "r"(af[mb][0]), "r"(af[mb][1]), "r"(af[mb][2]), "r"(af[mb][3]),
                          "r"(bf[nb][0]), "r"(bf[nb][1]));
                }
        }
        __syncthreads();
    }

#pragma unroll
    for (int nb = 0; nb < 4; nb++) {
        int n = nBase + warpN * 32 + nb * 8 + 2 * q;
        float bx = bi[n] + bh[n];
        float by = bi[n + 1] + bh[n + 1];
#pragma unroll
        for (int mb = 0; mb < 4; mb++) {
            int m = mBase + warpM * 64 + mb * 16 + g;
            *(float2*)(C + (size_t)m * NGATES + n) =
                make_float2(acc[mb][nb][0] + bx, acc[mb][nb][1] + by);
            *(float2*)(C + (size_t)(m + 8) * NGATES + n) =
                make_float2(acc[mb][nb][2] + bx, acc[mb][nb][3] + by);
        }
    }
}

// ---------------- LSTM recurrence (warp-local gates) ----------------
// grid = 64 blocks: dir = blockIdx.x>>5, b = blockIdx.x&31. 512 threads.
// Thread (warp w, lane l): gate_type = l&3, unit = w*8 + (l>>2).
// Gate row (within dir) = type*128 + unit. All 4 gates of a unit live in
// adjacent lanes -> c/h update via shfl_down(width=4), no cross-warp exchange.
// One __syncthreads per step; h_s double-buffered.
#define WS2PITCH 9
#define REC_SMEM ((256 + PF*512) * sizeof(float) + 512 * WS2PITCH * sizeof(ulonglong2))
__global__ __launch_bounds__(512, 1) void lstm_rec(
    const float* __restrict__ gates,     // [m][1024]
    const float* __restrict__ whh_layer, // [2][512][128]
    float* __restrict__ outp)            // [m][256]
{
    extern __shared__ float sm[];
    float* h_s = sm;                                   // 2 x 128 (double buffer)
    float* gring = sm + 256;                           // PF*512
    ulonglong2* Ws2 = (ulonglong2*)(sm + 256 + PF * 512);

    int j = threadIdx.x;
    int w = j >> 5, l = j & 31;
    int type = l & 3;
    int unit = w * 8 + (l >> 2);          // 0..127
    int grow = type * 128 + unit;         // gate row within direction
    int dir = blockIdx.x >> 5;
    int b = blockIdx.x & 31;
    const float* Wd = whh_layer + (size_t)dir * 512 * 128;

    // smem W: cols 0..31 of each gate row (indexed by raw row id)
    for (int idx = j; idx < 512 * 8; idx += 512) {
        int r = idx >> 3, q2 = idx & 7;
        Ws2[r * WS2PITCH + q2] = ((const ulonglong2*)(Wd + (size_t)r * 128))[q2];
    }
    // regs: cols 32..127 of this thread's gate row
    u64 Wreg[48];
    {
        const u64* wp = (const u64*)(Wd + (size_t)grow * 128 + 32);
#pragma unroll
        for (int i = 0; i < 48; i++) Wreg[i] = wp[i];
    }

    if (j < 256) h_s[j] = 0.f;
    float c = 0.f;
    __syncthreads();

    int tstep = dir ? -1 : 1;
    int t0 = dir ? (Tn - 1) : 0;

    // cp.async ring (slot layout: [d][j])
    unsigned ring = (unsigned)__cvta_generic_to_shared(gring) + ((unsigned)j << 2);
    const float* gld = gates + (size_t)t0 * (Bn * NGATES) + (size_t)b * NGATES + dir * NG + grow;
    long gstep = (long)tstep * (Bn * NGATES);
#pragma unroll
    for (int d = 0; d < PF; d++) {
        asm volatile("cp.async.ca.shared.global [%0], [%1], 4;\n"
                     "cp.async.commit_group;"
                     :: "r"(ring + ((unsigned)d << 11)), "l"(gld) : "memory");
        gld += gstep;
    }

    float* op = outp + ((size_t)t0 * Bn + b) * F2n + dir * Hn + unit;
    long ostep = (long)tstep * Bn * F2n;

    const ulonglong2* wr = Ws2 + grow * WS2PITCH;

    for (int s = 0; s < Tn; ++s) {
        asm volatile("cp.async.wait_group 3;" ::: "memory");
        float gin = gring[((s & 3) << 9) | j];

        if (s < Tn - PF) {
            asm volatile("cp.async.ca.shared.global [%0], [%1], 4;"
                         :: "r"(ring + (((unsigned)s & 3u) << 11)), "l"(gld) : "memory");
            gld += gstep;
        }
        asm volatile("cp.async.commit_group;" ::: "memory");

        const ulonglong2* hp = (const ulonglong2*)(h_s + ((s & 1) << 7));

        u64 acc0 = packf2(gin, 0.f);
        u64 acc1 = 0ull;
#pragma unroll
        for (int i = 0; i < 8; i++) {
            ulonglong2 w2 = wr[i];
            ulonglong2 h2 = hp[i];
            ffma2(acc0, w2.x, h2.x);
            ffma2(acc1, w2.y, h2.y);
        }
#pragma unroll
        for (int i = 0; i < 24; i++) {
            ulonglong2 h2 = hp[8 + i];
            ffma2(acc0, Wreg[2 * i], h2.x);
            ffma2(acc1, Wreg[2 * i + 1], h2.y);
        }
        float p0, p1, p2, p3;
        unpackf2(acc0, p0, p1);
        unpackf2(acc1, p2, p3);
        float accf = (p0 + p1) + (p2 + p3);

        // own-gate nonlinearity (sig via tanh for types 0,1,3; tanh for type 2)
        float arg = (type == 2) ? accf : 0.5f * accf;
        float tv = tanh_fast(arg);
        float a = (type == 2) ? tv : (0.5f * tv + 0.5f);

        // gather f,g,o into the i-lane of each 4-lane group
        float af = __shfl_down_sync(0xffffffffu, a, 1, 4);
        float ag = __shfl_down_sync(0xffffffffu, a, 2, 4);
        float ao = __shfl_down_sync(0xffffffffu, a, 3, 4);

        if (type == 0) {
            c = af * c + a * ag;
            float hN = ao * tanh_fast(c);
            h_s[((s & 1) ^ 1) << 7 | unit] = hN;
            *op = hN;
        }
        op += ostep;
        __syncthreads();
    }
}

// ---------------- attention prep ----------------
__global__ __launch_bounds__(256) void prep_kernel(
    const float* __restrict__ out2,
    const float* __restrict__ wq, const float* __restrict__ bq,
    const float* __restrict__ wk, const float* __restrict__ bk,
    const float* __restrict__ wv, const float* __restrict__ bv,
    const float* __restrict__ w_fc)
{
    __shared__ float osm[256];
    __shared__ float qsm[256];
    __shared__ float red[256];
    int tid = threadIdx.x;

    if (blockIdx.x < 32) {
        int b = blockIdx.x;
        osm[tid] = out2[((size_t)(Tn - 1) * Bn + b) * F2n + tid];
        __syncthreads();

        float q = bq[tid];
        const float* wrow = wq + (size_t)tid * 256;
        for (int e = 0; e < 256; e += 4) {
            float4 w4 = *(const float4*)(wrow + e);
            float4 o4 = *(const float4*)(osm + e);
            q += w4.x * o4.x + w4.y * o4.y + w4.z * o4.z + w4.w * o4.w;
        }
        qsm[tid] = q;
        __syncthreads();

        float acc = 0.f;
        for (int d = 0; d < 256; d++) acc += qsm[d] * wk[(size_t)d * 256 + tid];
        g_kq[b * 256 + tid] = acc;

        red[tid] = qsm[tid] * bk[tid];
        __syncthreads();
        for (int st = 128; st > 0; st >>= 1) {
            if (tid < st) red[tid] += red[tid + st];
            __syncthreads();
        }
        if (tid == 0) g_qbk[b] = red[0];
    } else {
#pragma unroll
        for (int cc = 0; cc < 4; cc++) {
            float acc = 0.f;
            for (int d = 0; d < 256; d++) acc += w_fc[cc * 256 + d] * wv[(size_t)d * 256 + tid];
            g_vw[cc * 256 + tid] = acc;
        }
        if (tid < 4) {
            float a = 0.f;
            for (int d = 0; d < 256; d++) a += w_fc[tid * 256 + d] * bv[d];
            g_vb[tid] = a;
        }
    }
}

// ---------------- fused attention + FC (last query only) ----------------
__global__ __launch_bounds__(256) void attn_kernel(
    const float* __restrict__ out2,
    const float* __restrict__ b_fc,
    float* __restrict__ outp)
{
    __shared__ float kqs[256];
    __shared__ float vws[4 * 256];
    __shared__ float rm[256], rd[256];
    __shared__ float ra[4][256];
    int b = blockIdx.x, tid = threadIdx.x;

    kqs[tid] = g_kq[b * 256 + tid];
#pragma unroll
    for (int cc = 0; cc < 4; cc++) vws[cc * 256 + tid] = g_vw[cc * 256 + tid];
    float qbk = g_qbk[b];
    __syncthreads();

    float m = -1e30f, den = 0.f, a0 = 0.f, a1 = 0.f, a2 = 0.f, a3 = 0.f;
    for (int t = tid; t < Tn; t += 256) {
        const float* row = out2 + ((size_t)t * Bn + b) * F2n;
        float s = 0.f, u0 = 0.f, u1 = 0.f, u2 = 0.f, u3 = 0.f;
        for (int e = 0; e < 256; e += 4) {
            float4 r = *(const float4*)(row + e);
            s  += r.x * kqs[e]   + r.y * kqs[e+1]   + r.z * kqs[e+2]   + r.w * kqs[e+3];
            u0 += r.x * vws[e]   + r.y * vws[e+1]   + r.z * vws[e+2]   + r.w * vws[e+3];
            u1 += r.x * vws[256+e] + r.y * vws[256+e+1] + r.z * vws[256+e+2] + r.w * vws[256+e+3];
            u2 += r.x * vws[512+e] + r.y * vws[512+e+1] + r.z * vws[512+e+2] + r.w * vws[512+e+3];
            u3 += r.x * vws[768+e] + r.y * vws[768+e+1] + r.z * vws[768+e+2] + r.w * vws[768+e+3];
        }
        s = (s + qbk) * 0.0625f;   // 1/sqrt(256)
        float nm = fmaxf(m, s);
        float sc = __expf(m - nm);
        float w  = __expf(s - nm);
        den = den * sc + w;
        a0 = a0 * sc + w * u0;
        a1 = a1 * sc + w * u1;
        a2 = a2 * sc + w * u2;
        a3 = a3 * sc + w * u3;
        m = nm;
    }
    rm[tid] = m; rd[tid] = den;
    ra[0][tid] = a0; ra[1][tid] = a1; ra[2][tid] = a2; ra[3][tid] = a3;
    __syncthreads();
    for (int st = 128; st > 0; st >>= 1) {
        if (tid < st) {
            float m2 = fmaxf(rm[tid], rm[tid + st]);
            float s1 = __expf(rm[tid] - m2);
            float s2 = __expf(rm[tid + st] - m2);
            rd[tid] = rd[tid] * s1 + rd[tid + st] * s2;
#pragma unroll
            for (int cc = 0; cc < 4; cc++)
                ra[cc][tid] = ra[cc][tid] * s1 + ra[cc][tid + st] * s2;
            rm[tid] = m2;
        }
        __syncthreads();
    }
    if (tid < 4) {
        outp[b * 4 + tid] = ra[tid][0] / rd[0] + g_vb[tid] + b_fc[tid];
    }
}

// ---------------- launcher ----------------
extern "C" void kernel_launch(void* const* d_in, const int* in_sizes, int n_in,
                              void* d_out, int out_size)
{
    const float* x    = (const float*)d_in[0];   // (32,1024,256)
    const float* w_ih = (const float*)d_in[1];   // (2,2,512,256)
    const float* w_hh = (const float*)d_in[2];   // (2,2,512,128)
    const float* b_ih = (const float*)d_in[3];   // (2,2,512)
    const float* b_hh = (const float*)d_in[4];   // (2,2,512)
    const float* wq   = (const float*)d_in[5];
    const float* wk   = (const float*)d_in[6];
    const float* wv   = (const float*)d_in[7];
    const float* bq   = (const float*)d_in[8];
    const float* bk   = (const float*)d_in[9];
    const float* bv   = (const float*)d_in[10];
    const float* w_fc = (const float*)d_in[11];
    const float* b_fc = (const float*)d_in[12];
    float* outp = (float*)d_out;

    float *p_gates, *p_out1, *p_out2;
    cudaGetSymbolAddress((void**)&p_gates, g_gates);
    cudaGetSymbolAddress((void**)&p_out1, g_out1);
    cudaGetSymbolAddress((void**)&p_out2, g_out2);

    cudaFuncSetAttribute(lstm_rec, cudaFuncAttributeMaxDynamicSharedMemorySize, (int)REC_SMEM);

    dim3 ggrid(8, 256);   // x = n-tile, y = m-tile

    // layer 1: A = x, row (t,b) -> x + b*(1024*256) + t*256
    gemm_tf32<<<ggrid, 256>>>(x, (size_t)Tn * INn, (size_t)INn,
                              w_ih, b_ih, b_hh, p_gates);
    lstm_rec<<<64, 512, REC_SMEM>>>(p_gates, w_hh, p_out1);

    // layer 2: A = out1, row (t,b) -> out1 + b*256 + t*(32*256)
    gemm_tf32<<<ggrid, 256>>>(p_out1, (size_t)F2n, (size_t)Bn * F2n,
                              w_ih + 2 * 512 * 256, b_ih + 1024, b_hh + 1024, p_gates);
    lstm_rec<<<64, 512, REC_SMEM>>>(p_gates, w_hh + 2 * 512 * 128, p_out2);

    prep_kernel<<<33, 256>>>(p_out2, wq, bq, wk, bk, wv, bv, w_fc);
    attn_kernel<<<32, 256>>>(p_out2, b_fc, outp);
}

// round 5
// speedup vs baseline: 1.6055x; 1.6055x over previous
#include <cuda_runtime.h>
#include <cuda_bf16.h>
#include <math.h>

// Problem constants
#define Bn 32
#define Tn 1024
#define INn 256
#define Hn 128
#define F2n 256
#define NG 512           // 4*H gates per direction
#define NGATES 1024      // both directions
#define Mrows (Tn*Bn)    // 32768
#define PF 4             // gin prefetch depth

typedef unsigned long long u64;

// ---------------- device scratch (no allocs allowed) ----------------
__device__ float g_gates[(size_t)Mrows * NGATES];   // [m][dir*512+g], m = t*32+b
__device__ float g_out1[(size_t)Mrows * F2n];       // [t*32+b][256]
__device__ float g_out2[(size_t)Mrows * F2n];
__device__ float g_kq[Bn * F2n];
__device__ float g_qbk[Bn];
__device__ float g_vw[4 * F2n];
__device__ float g_vb[4];

// ---------------- helpers ----------------
__device__ __forceinline__ float tanh_fast(float x) {
    float r;
    asm("tanh.approx.f32 %0, %1;" : "=f"(r) : "f"(x));
    return r;
}
__device__ __forceinline__ unsigned f2tf32(float f) {
    unsigned u;
    asm("cvt.rna.tf32.f32 %0, %1;" : "=r"(u) : "f"(f));
    return u;
}
__device__ __forceinline__ void ffma2(u64& acc, u64 a, u64 b) {
    asm("fma.rn.f32x2 %0, %1, %2, %0;" : "+l"(acc) : "l"(a), "l"(b));
}
__device__ __forceinline__ u64 packf2(float lo, float hi) {
    u64 r;
    asm("mov.b64 %0, {%1, %2};" : "=l"(r) : "f"(lo), "f"(hi));
    return r;
}
__device__ __forceinline__ void unpackf2(u64 v, float& lo, float& hi) {
    asm("mov.b64 {%0, %1}, %2;" : "=f"(lo), "=f"(hi) : "l"(v));
}

// ---------------- tf32 tensor-core GEMM: gates = A @ W^T + (bi+bh) ----------------
__device__ __forceinline__ int sidx(int r, int k) {
    return r * 32 + ((((k >> 2) ^ (r & 7)) & 7) << 2) + (k & 3);
}

__global__ __launch_bounds__(256) void gemm_tf32(
    const float* __restrict__ A, size_t sB, size_t sT,
    const float* __restrict__ W,
    const float* __restrict__ bi, const float* __restrict__ bh,
    float* __restrict__ C)
{
    __shared__ unsigned sA[128 * 32];
    __shared__ unsigned sW[128 * 32];

    int tid = threadIdx.x;
    int wid = tid >> 5, lane = tid & 31;
    int g = lane >> 2, q = lane & 3;
    int warpM = wid & 1, warpN = wid >> 1;
    int mBase = blockIdx.y * 128;
    int nBase = blockIdx.x * 128;

    float acc[4][4][4];
#pragma unroll
    for (int mb = 0; mb < 4; mb++)
#pragma unroll
        for (int nb = 0; nb < 4; nb++)
#pragma unroll
            for (int i = 0; i < 4; i++) acc[mb][nb][i] = 0.f;

    int lrow = tid >> 3;
    int lseg = tid & 7;

    const float* Arows[4];
    const float* Wrows[4];
#pragma unroll
    for (int i = 0; i < 4; i++) {
        int r = lrow + 32 * i;
        int m = mBase + r;
        int bb = m & 31, tt = m >> 5;
        Arows[i] = A + (size_t)bb * sB + (size_t)tt * sT + lseg * 4;
        Wrows[i] = W + (size_t)(nBase + r) * 256 + lseg * 4;
    }
    int soff[4];
#pragma unroll
    for (int i = 0; i < 4; i++) {
        int r = lrow + 32 * i;
        soff[i] = r * 32 + (((lseg ^ (r & 7)) & 7) << 2);
    }

    float4 av[4], wv[4];
#pragma unroll
    for (int i = 0; i < 4; i++) {
        av[i] = *(const float4*)(Arows[i]);
        wv[i] = *(const float4*)(Wrows[i]);
    }

    for (int kb = 0; kb < 256; kb += 32) {
#pragma unroll
        for (int i = 0; i < 4; i++) {
            *(uint4*)&sA[soff[i]] = make_uint4(f2tf32(av[i].x), f2tf32(av[i].y), f2tf32(av[i].z), f2tf32(av[i].w));
            *(uint4*)&sW[soff[i]] = make_uint4(f2tf32(wv[i].x), f2tf32(wv[i].y), f2tf32(wv[i].z), f2tf32(wv[i].w));
        }
        __syncthreads();

        if (kb + 32 < 256) {
#pragma unroll
            for (int i = 0; i < 4; i++) {
                av[i] = *(const float4*)(Arows[i] + kb + 32);
                wv[i] = *(const float4*)(Wrows[i] + kb + 32);
            }
        }

#pragma unroll
        for (int kk = 0; kk < 4; kk++) {
            unsigned af[4][4], bf[4][2];
#pragma unroll
            for (int mb = 0; mb < 4; mb++) {
                int r = warpM * 64 + mb * 16 + g;
                af[mb][0] = sA[sidx(r,     kk * 8 + q)];
                af[mb][1] = sA[sidx(r + 8, kk * 8 + q)];
                af[mb][2] = sA[sidx(r,     kk * 8 + q + 4)];
                af[mb][3] = sA[sidx(r + 8, kk * 8 + q + 4)];
            }
#pragma unroll
            for (int nb = 0; nb < 4; nb++) {
                int n = warpN * 32 + nb * 8 + g;
                bf[nb][0] = sW[sidx(n, kk * 8 + q)];
                bf[nb][1] = sW[sidx(n, kk * 8 + q + 4)];
            }
#pragma unroll
            for (int mb = 0; mb < 4; mb++)
#pragma unroll
                for (int nb = 0; nb < 4; nb++) {
                    asm volatile(
                        "mma.sync.aligned.m16n8k8.row.col.f32.tf32.tf32.f32 "
                        "{%0,%1,%2,%3}, {%4,%5,%6,%7}, {%8,%9}, {%0,%1,%2,%3};"
                        : "+f"(acc[mb][nb][0]), "+f"(acc[mb][nb][1]),
                          "+f"(acc[mb][nb][2]), "+f"(acc[mb][nb][3])
                        : "r"(af[mb][0]), "r"(af[mb][1]), "r"(af[mb][2]), "r"(af[mb][3]),
                          "r"(bf[nb][0]), "r"(bf[nb][1]));
                }
        }
        __syncthreads();
    }

#pragma unroll
    for (int nb = 0; nb < 4; nb++) {
        int n = nBase + warpN * 32 + nb * 8 + 2 * q;
        float bx = bi[n] + bh[n];
        float by = bi[n + 1] + bh[n + 1];
#pragma unroll
        for (int mb = 0; mb < 4; mb++) {
            int m = mBase + warpM * 64 + mb * 16 + g;
            *(float2*)(C + (size_t)m * NGATES + n) =
                make_float2(acc[mb][nb][0] + bx, acc[mb][nb][1] + by);
            *(float2*)(C + (size_t)(m + 8) * NGATES + n) =
                make_float2(acc[mb][nb][2] + bx, acc[mb][nb][3] + by);
        }
    }
}

// ---------------- LSTM recurrence (warp-local gates, permuted W layout) ----------------
// grid = 64 blocks: dir = blockIdx.x>>5, b = blockIdx.x&31. 512 threads.
// Thread (warp w, lane l): gate_type = l&3, unit = w*8 + (l>>2).
// Gate row (within dir) = type*128 + unit.
// smem W is stored PERMUTED: physical slot j holds row grow(j) -> access is
// Ws2 + j*pitch = linear, conflict-free (same banks as the R3 layout).
// c/h update: 2 shfl_xor, c replicated on the i/f lanes, one barrier per step.
#define WS2PITCH 9
#define REC_SMEM ((256 + PF*512) * sizeof(float) + 512 * WS2PITCH * sizeof(ulonglong2))
__global__ __launch_bounds__(512, 1) void lstm_rec(
    const float* __restrict__ gates,     // [m][1024]
    const float* __restrict__ whh_layer, // [2][512][128]
    float* __restrict__ outp)            // [m][256]
{
    extern __shared__ float sm[];
    float* h_s = sm;                                   // 2 x 128 (double buffer)
    float* gring = sm + 256;                           // PF*512
    ulonglong2* Ws2 = (ulonglong2*)(sm + 256 + PF * 512);

    int j = threadIdx.x;
    int w = j >> 5, l = j & 31;
    int type = l & 3;
    int unit = w * 8 + (l >> 2);          // 0..127
    int grow = type * 128 + unit;         // gate row within direction
    int dir = blockIdx.x >> 5;
    int b = blockIdx.x & 31;
    const float* Wd = whh_layer + (size_t)dir * 512 * 128;

    // smem W: cols 0..31, PERMUTED so slot s holds row grow(s)
    for (int idx = j; idx < 512 * 8; idx += 512) {
        int slot = idx >> 3, q2 = idx & 7;
        int ls = slot & 31;
        int rowS = (ls & 3) * 128 + (slot >> 5) * 8 + (ls >> 2);
        Ws2[slot * WS2PITCH + q2] = ((const ulonglong2*)(Wd + (size_t)rowS * 128))[q2];
    }
    // regs: cols 32..127 of this thread's gate row
    u64 Wreg[48];
    {
        const u64* wp = (const u64*)(Wd + (size_t)grow * 128 + 32);
#pragma unroll
        for (int i = 0; i < 48; i++) Wreg[i] = wp[i];
    }

    if (j < 256) h_s[j] = 0.f;
    float c = 0.f;
    __syncthreads();

    int tstep = dir ? -1 : 1;
    int t0 = dir ? (Tn - 1) : 0;

    // cp.async ring (slot layout: [d][j])
    unsigned ring = (unsigned)__cvta_generic_to_shared(gring) + ((unsigned)j << 2);
    const float* gld = gates + (size_t)t0 * (Bn * NGATES) + (size_t)b * NGATES + dir * NG + grow;
    long gstep = (long)tstep * (Bn * NGATES);
#pragma unroll
    for (int d = 0; d < PF; d++) {
        asm volatile("cp.async.ca.shared.global [%0], [%1], 4;\n"
                     "cp.async.commit_group;"
                     :: "r"(ring + ((unsigned)d << 11)), "l"(gld) : "memory");
        gld += gstep;
    }

    float* op = outp + ((size_t)t0 * Bn + b) * F2n + dir * Hn + unit;
    long ostep = (long)tstep * Bn * F2n;

    const ulonglong2* wr = Ws2 + j * WS2PITCH;   // linear -> conflict-free

    for (int s = 0; s < Tn; ++s) {
        asm volatile("cp.async.wait_group 3;" ::: "memory");
        float gin = gring[((s & 3) << 9) | j];

        if (s < Tn - PF) {
            asm volatile("cp.async.ca.shared.global [%0], [%1], 4;"
                         :: "r"(ring + (((unsigned)s & 3u) << 11)), "l"(gld) : "memory");
            gld += gstep;
        }
        asm volatile("cp.async.commit_group;" ::: "memory");

        const ulonglong2* hp = (const ulonglong2*)(h_s + ((s & 1) << 7));

        u64 acc0 = packf2(gin, 0.f);
        u64 acc1 = 0ull;
#pragma unroll
        for (int i = 0; i < 8; i++) {
            ulonglong2 w2 = wr[i];
            ulonglong2 h2 = hp[i];
            ffma2(acc0, w2.x, h2.x);
            ffma2(acc1, w2.y, h2.y);
        }
#pragma unroll
        for (int i = 0; i < 24; i++) {
            ulonglong2 h2 = hp[8 + i];
            ffma2(acc0, Wreg[2 * i], h2.x);
            ffma2(acc1, Wreg[2 * i + 1], h2.y);
        }
        float p0, p1, p2, p3;
        unpackf2(acc0, p0, p1);
        unpackf2(acc1, p2, p3);
        float accf = (p0 + p1) + (p2 + p3);

        // own-gate nonlinearity: types 0,1,3 sigmoid, type 2 tanh
        float arg = (type == 2) ? accf : 0.5f * accf;
        float tv = tanh_fast(arg);
        float a = (type == 2) ? tv : (0.5f * tv + 0.5f);

        // 2-shfl c/h update; c replicated on lanes type 0 and 1 of each quad
        float r1 = __shfl_xor_sync(0xffffffffu, a, 2, 4); // lane-i gets tanh(g), lane-f gets sig(o)
        float p = (type == 0) ? (a * r1)    // u = sig(i)*tanh(g)
                              : (a * c);    // v = sig(f)*c   (lane-f; lanes 2,3 garbage)
        float r2 = __shfl_xor_sync(0xffffffffu, p, 1, 4); // i<->f exchange u,v
        c = p + r2;                          // lanes 0,1: new cell state (identical)

        if (type == 1) {
            float hN = r1 * tanh_fast(c);    // r1 = sig(o) on lane-f
            h_s[(((s & 1) ^ 1) << 7) | unit] = hN;
            *op = hN;
        }
        op += ostep;
        __syncthreads();
    }
}

// ---------------- attention prep ----------------
__global__ __launch_bounds__(256) void prep_kernel(
    const float* __restrict__ out2,
    const float* __restrict__ wq, const float* __restrict__ bq,
    const float* __restrict__ wk, const float* __restrict__ bk,
    const float* __restrict__ wv, const float* __restrict__ bv,
    const float* __restrict__ w_fc)
{
    __shared__ float osm[256];
    __shared__ float qsm[256];
    __shared__ float red[256];
    int tid = threadIdx.x;

    if (blockIdx.x < 32) {
        int b = blockIdx.x;
        osm[tid] = out2[((size_t)(Tn - 1) * Bn + b) * F2n + tid];
        __syncthreads();

        float q = bq[tid];
        const float* wrow = wq + (size_t)tid * 256;
        for (int e = 0; e < 256; e += 4) {
            float4 w4 = *(const float4*)(wrow + e);
            float4 o4 = *(const float4*)(osm + e);
            q += w4.x * o4.x + w4.y * o4.y + w4.z * o4.z + w4.w * o4.w;
        }
        qsm[tid] = q;
        __syncthreads();

        float acc = 0.f;
        for (int d = 0; d < 256; d++) acc += qsm[d] * wk[(size_t)d * 256 + tid];
        g_kq[b * 256 + tid] = acc;

        red[tid] = qsm[tid] * bk[tid];
        __syncthreads();
        for (int st = 128; st > 0; st >>= 1) {
            if (tid < st) red[tid] += red[tid + st];
            __syncthreads();
        }
        if (tid == 0) g_qbk[b] = red[0];
    } else {
#pragma unroll
        for (int cc = 0; cc < 4; cc++) {
            float acc = 0.f;
            for (int d = 0; d < 256; d++) acc += w_fc[cc * 256 + d] * wv[(size_t)d * 256 + tid];
            g_vw[cc * 256 + tid] = acc;
        }
        if (tid < 4) {
            float a = 0.f;
            for (int d = 0; d < 256; d++) a += w_fc[tid * 256 + d] * bv[d];
            g_vb[tid] = a;
        }
    }
}

// ---------------- fused attention + FC (last query only) ----------------
__global__ __launch_bounds__(256) void attn_kernel(
    const float* __restrict__ out2,
    const float* __restrict__ b_fc,
    float* __restrict__ outp)
{
    __shared__ float kqs[256];
    __shared__ float vws[4 * 256];
    __shared__ float rm[256], rd[256];
    __shared__ float ra[4][256];
    int b = blockIdx.x, tid = threadIdx.x;

    kqs[tid] = g_kq[b * 256 + tid];
#pragma unroll
    for (int cc = 0; cc < 4; cc++) vws[cc * 256 + tid] = g_vw[cc * 256 + tid];
    float qbk = g_qbk[b];
    __syncthreads();

    float m = -1e30f, den = 0.f, a0 = 0.f, a1 = 0.f, a2 = 0.f, a3 = 0.f;
    for (int t = tid; t < Tn; t += 256) {
        const float* row = out2 + ((size_t)t * Bn + b) * F2n;
        float s = 0.f, u0 = 0.f, u1 = 0.f, u2 = 0.f, u3 = 0.f;
        for (int e = 0; e < 256; e += 4) {
            float4 r = *(const float4*)(row + e);
            s  += r.x * kqs[e]   + r.y * kqs[e+1]   + r.z * kqs[e+2]   + r.w * kqs[e+3];
            u0 += r.x * vws[e]   + r.y * vws[e+1]   + r.z * vws[e+2]   + r.w * vws[e+3];
            u1 += r.x * vws[256+e] + r.y * vws[256+e+1] + r.z * vws[256+e+2] + r.w * vws[256+e+3];
            u2 += r.x * vws[512+e] + r.y * vws[512+e+1] + r.z * vws[512+e+2] + r.w * vws[512+e+3];
            u3 += r.x * vws[768+e] + r.y * vws[768+e+1] + r.z * vws[768+e+2] + r.w * vws[768+e+3];
        }
        s = (s + qbk) * 0.0625f;   // 1/sqrt(256)
        float nm = fmaxf(m, s);
        float sc = __expf(m - nm);
        float w  = __expf(s - nm);
        den = den * sc + w;
        a0 = a0 * sc + w * u0;
        a1 = a1 * sc + w * u1;
        a2 = a2 * sc + w * u2;
        a3 = a3 * sc + w * u3;
        m = nm;
    }
    rm[tid] = m; rd[tid] = den;
    ra[0][tid] = a0; ra[1][tid] = a1; ra[2][tid] = a2; ra[3][tid] = a3;
    __syncthreads();
    for (int st = 128; st > 0; st >>= 1) {
        if (tid < st) {
            float m2 = fmaxf(rm[tid], rm[tid + st]);
            float s1 = __expf(rm[tid] - m2);
            float s2 = __expf(rm[tid + st] - m2);
            rd[tid] = rd[tid] * s1 + rd[tid + st] * s2;
#pragma unroll
            for (int cc = 0; cc < 4; cc++)
                ra[cc][tid] = ra[cc][tid] * s1 + ra[cc][tid + st] * s2;
            rm[tid] = m2;
        }
        __syncthreads();
    }
    if (tid < 4) {
        outp[b * 4 + tid] = ra[tid][0] / rd[0] + g_vb[tid] + b_fc[tid];
    }
}

// ---------------- launcher ----------------
extern "C" void kernel_launch(void* const* d_in, const int* in_sizes, int n_in,
                              void* d_out, int out_size)
{
    const float* x    = (const float*)d_in[0];   // (32,1024,256)
    const float* w_ih = (const float*)d_in[1];   // (2,2,512,256)
    const float* w_hh = (const float*)d_in[2];   // (2,2,512,128)
    const float* b_ih = (const float*)d_in[3];   // (2,2,512)
    const float* b_hh = (const float*)d_in[4];   // (2,2,512)
    const float* wq   = (const float*)d_in[5];
    const float* wk   = (const float*)d_in[6];
    const float* wv   = (const float*)d_in[7];
    const float* bq   = (const float*)d_in[8];
    const float* bk   = (const float*)d_in[9];
    const float* bv   = (const float*)d_in[10];
    const float* w_fc = (const float*)d_in[11];
    const float* b_fc = (const float*)d_in[12];
    float* outp = (float*)d_out;

    float *p_gates, *p_out1, *p_out2;
    cudaGetSymbolAddress((void**)&p_gates, g_gates);
    cudaGetSymbolAddress((void**)&p_out1, g_out1);
    cudaGetSymbolAddress((void**)&p_out2, g_out2);

    cudaFuncSetAttribute(lstm_rec, cudaFuncAttributeMaxDynamicSharedMemorySize, (int)REC_SMEM);

    dim3 ggrid(8, 256);   // x = n-tile, y = m-tile

    // layer 1: A = x, row (t,b) -> x + b*(1024*256) + t*256
    gemm_tf32<<<ggrid, 256>>>(x, (size_t)Tn * INn, (size_t)INn,
                              w_ih, b_ih, b_hh, p_gates);
    lstm_rec<<<64, 512, REC_SMEM>>>(p_gates, w_hh, p_out1);

    // layer 2: A = out1, row (t,b) -> out1 + b*256 + t*(32*256)
    gemm_tf32<<<ggrid, 256>>>(p_out1, (size_t)F2n, (size_t)Bn * F2n,
                              w_ih + 2 * 512 * 256, b_ih + 1024, b_hh + 1024, p_gates);
    lstm_rec<<<64, 512, REC_SMEM>>>(p_gates, w_hh + 2 * 512 * 128, p_out2);

    prep_kernel<<<33, 256>>>(p_out2, wq, bq, wk, bk, wv, bv, w_fc);
    attn_kernel<<<32, 256>>>(p_out2, b_fc, outp);
}